// round 17
// baseline (speedup 1.0000x reference)
#include <cuda_runtime.h>
#include <cstdint>

// ProdEinsumTC: out[a,b,c,d,g] = (1/3) * sum_{e,f} T1[a,b,c,d,e,f] * T2[b,c,e,f,g]
// T1: (4, 131072, 6, 27) fp32   T2: (131072, 6, 27) fp32   out: (4, 131072, 6, 9)
//
// R17 (= R16 resubmitted after infra failure): proven warp-autonomous
// issue-once structure, WBC=16 (doubled warp tile) to double every contiguous
// DRAM run:
//  - reads: 5 segments x 1728B contiguous (was 864B); writes: 576B/path (was 288B)
//    -> fewer page activates and R/W turnaround points per byte.
//  - 128-thread blocks, 4 warps x 8.64KB = 34.56KB smem -> 6 blocks/SM = 48 warps
//    (the proven residency). launch_bounds(128,6): 85-reg budget, no spills.
//  - Compute in two halves (bcl, bcl+8), both accumulated before staging;
//    staged STG.128 output (36 float4 contiguous per path per warp).

#define BC        786432
#define BC27      ((size_t)BC * 27)
#define BC9       ((size_t)BC * 9)
#define WBC       16                // bc pairs per warp
#define WARPS     4                 // warps per block
#define NTHREADS  (WARPS * 32)
#define WARP_F    (WBC * 27 * 5)    // 2160 floats per warp region (4xT1 + T2)
#define SEG_V4    (WBC * 27 / 4)    // 108 float4 per segment
#define NORM      (0.3333333333333333f)

__device__ __forceinline__ void cp_async16(uint32_t dst, const void* src) {
    asm volatile("cp.async.cg.shared.global [%0], [%1], 16;\n"
                 :: "r"(dst), "l"(src));
}
__device__ __forceinline__ uint32_t smem_u32(const void* p) {
    uint32_t a;
    asm("{ .reg .u64 t; cvta.to.shared.u64 t, %1; cvt.u32.u64 %0, t; }"
        : "=r"(a) : "l"(p));
    return a;
}

__global__ __launch_bounds__(NTHREADS, 6)
void prod_einsum_kernel(const float* __restrict__ T1,
                        const float* __restrict__ T2,
                        float* __restrict__ out)
{
    __shared__ __align__(16) float smem[WARPS * WARP_F];   // 34560 B

    const int tid  = threadIdx.x;
    const int w    = tid >> 5;
    const int lane = tid & 31;

    float* const swarp = smem + w * WARP_F;
    const uint32_t sw_u32 = smem_u32(swarp);

    const size_t bc0 = ((size_t)blockIdx.x * WARPS + w) * WBC;

    // ---- Stage: 5 segments x 108 float4 (1728B contiguous each) ----
    // Layout: [a=0..3][bcl 0..15][27] then [T2][bcl][27] at offset 4*432
    #pragma unroll
    for (int a = 0; a < 4; ++a) {
        const float4* __restrict__ g1 =
            (const float4*)(T1 + (size_t)a * BC27 + bc0 * 27);
        #pragma unroll
        for (int r = 0; r < 3; ++r)
            cp_async16(sw_u32 + (a * SEG_V4 + r * 32 + lane) * 16,
                       g1 + r * 32 + lane);
        if (lane < 12)
            cp_async16(sw_u32 + (a * SEG_V4 + 96 + lane) * 16, g1 + 96 + lane);
    }
    {
        const float4* __restrict__ g2 = (const float4*)(T2 + bc0 * 27);
        #pragma unroll
        for (int r = 0; r < 3; ++r)
            cp_async16(sw_u32 + (4 * SEG_V4 + r * 32 + lane) * 16,
                       g2 + r * 32 + lane);
        if (lane < 12)
            cp_async16(sw_u32 + (4 * SEG_V4 + 96 + lane) * 16, g2 + 96 + lane);
    }
    asm volatile("cp.async.commit_group;\n");
    asm volatile("cp.async.wait_group 0;\n" ::: "memory");
    __syncwarp();

    // ---- Compute: lane = (a, bcl); two halves bcl and bcl+8 ----
    const int a   = lane >> 3;     // 0..3
    const int bcl = lane & 7;      // 0..7

    float acc0[9], acc1[9];
    #pragma unroll
    for (int i = 0; i < 9; ++i) { acc0[i] = 0.0f; acc1[i] = 0.0f; }

    #pragma unroll
    for (int h = 0; h < 2; ++h) {
        const int b2 = bcl + h * 8;
        const float* __restrict__ t1p = swarp + a * 432 + b2 * 27;  // [d][e][f]
        const float* __restrict__ t2p = swarp + 1728 + b2 * 27;     // [e][f][g]
        float* acc = h ? acc1 : acc0;

        #pragma unroll
        for (int k = 0; k < 9; ++k) {                 // k = e*3 + f
            const float b0v = t2p[k * 3 + 0];
            const float b1v = t2p[k * 3 + 1];
            const float b2v = t2p[k * 3 + 2];
            #pragma unroll
            for (int d = 0; d < 3; ++d) {
                const float av = t1p[d * 9 + k];
                acc[d * 3 + 0] = fmaf(av, b0v, acc[d * 3 + 0]);
                acc[d * 3 + 1] = fmaf(av, b1v, acc[d * 3 + 1]);
                acc[d * 3 + 2] = fmaf(av, b2v, acc[d * 3 + 2]);
            }
        }
    }

    // ---- Stage outputs: [a][bc 0..15][9] = 576 floats, then STG.128 ----
    __syncwarp();                   // all smem reads done -> safe to overwrite
    #pragma unroll
    for (int j = 0; j < 9; ++j) {
        swarp[a * 144 + bcl * 9 + j]       = acc0[j] * NORM;
        swarp[a * 144 + (bcl + 8) * 9 + j] = acc1[j] * NORM;
    }
    __syncwarp();

    #pragma unroll
    for (int aa = 0; aa < 4; ++aa) {
        float4* __restrict__ o = (float4*)(out + (size_t)aa * BC9 + bc0 * 9);
        o[lane] = *(const float4*)(swarp + aa * 144 + lane * 4);   // 32 of 36
        if (lane < 4)
            o[32 + lane] = *(const float4*)(swarp + aa * 144 + (32 + lane) * 4);
    }
}

extern "C" void kernel_launch(void* const* d_in, const int* in_sizes, int n_in,
                              void* d_out, int out_size)
{
    const float* T1 = (const float*)d_in[0];
    const float* T2 = (const float*)d_in[1];
    float* out = (float*)d_out;

    const int nblocks = BC / (WARPS * WBC);   // 12288
    prod_einsum_kernel<<<nblocks, NTHREADS>>>(T1, T2, out);
}